// round 5
// baseline (speedup 1.0000x reference)
#include <cuda_runtime.h>
#include <math.h>

#define NN 50000
#define NE 800000
#define KF 128          // IN_F
#define HF 128          // HEADS * OUT_F
#define NH 4
#define OF 32
#define EF 32
#define NBLK 196        // ceil(NN/256)

// ---------------- scratch (device globals: allocation-free) ----------------
__device__ float g_ht[(size_t)NN * HF];                 // 25.6 MB
__device__ __align__(16) float g_ai[NN * NH];
__device__ __align__(16) float g_aj[NN * NH];
__device__ __align__(16) float g_s[(size_t)NE * NH];    // raw scores, ROW-SORTED
__device__ int   g_col[NE];                             // sorted -> col
__device__ int   g_eid[NE];                             // sorted -> edge id
__device__ int   g_cnt[NN];
__device__ int   g_pre[NN];
__device__ int   g_off[NN];
__device__ int   g_pos[NN];
__device__ int   g_bsum[NBLK];
__device__ int   g_boff[NBLK];
__device__ float g_vc[NH * EF + NH];
__device__ unsigned int g_maxbits;

__device__ __forceinline__ unsigned f2o(float x) {
    unsigned u = __float_as_uint(x);
    return (u & 0x80000000u) ? ~u : (u | 0x80000000u);
}
__device__ __forceinline__ float o2f(unsigned u) {
    return __uint_as_float((u & 0x80000000u) ? (u & 0x7fffffffu) : ~u);
}

// ---------------- kernel 0: init (zero counts, compute v/c, reset max) -----
__global__ void k_init(const float* __restrict__ eW, const float* __restrict__ a,
                       const float* __restrict__ eb) {
    int idx = blockIdx.x * blockDim.x + threadIdx.x;
    for (int i = idx; i < NN; i += gridDim.x * blockDim.x) g_cnt[i] = 0;
    if (blockIdx.x == 0) {
        int t = threadIdx.x;
        if (t < NH * EF) {
            int h = t >> 5, k = t & 31;
            float s = 0.0f;
            #pragma unroll
            for (int f = 0; f < OF; f++)
                s += eW[k * HF + h * OF + f] * a[h * 96 + 64 + f];
            g_vc[t] = s;
        } else if (t < NH * EF + NH) {
            int h = t - NH * EF;
            float s = 0.0f;
            #pragma unroll
            for (int f = 0; f < OF; f++)
                s += eb[h * OF + f] * a[h * 96 + 64 + f];
            g_vc[NH * EF + h] = s;
        } else if (t == NH * EF + NH) {
            g_maxbits = 0u;
        }
    }
}

// ---------------- kernel 1: row histogram (needs only edge_indices) --------
__global__ __launch_bounds__(256) void k_count(const int* __restrict__ ei) {
    int e = blockIdx.x * blockDim.x + threadIdx.x;
    if (e < NE) atomicAdd(&g_cnt[ei[e]], 1);
}

// ---------------- scan stage 1 ---------------------------------------------
__global__ __launch_bounds__(256) void k_scan1() {
    __shared__ int sh[256];
    int t = threadIdx.x;
    int i = blockIdx.x * 256 + t;
    int c = (i < NN) ? g_cnt[i] : 0;
    sh[t] = c;
    __syncthreads();
    #pragma unroll
    for (int o = 1; o < 256; o <<= 1) {
        int v = (t >= o) ? sh[t - o] : 0;
        __syncthreads();
        sh[t] += v;
        __syncthreads();
    }
    if (i < NN) g_pre[i] = sh[t] - c;
    if (t == 255) g_bsum[blockIdx.x] = sh[255];
}

// ---------------- scan stage 2 ---------------------------------------------
__global__ __launch_bounds__(256) void k_scan2() {
    __shared__ int sh[256];
    int t = threadIdx.x;
    int c = (t < NBLK) ? g_bsum[t] : 0;
    sh[t] = c;
    __syncthreads();
    #pragma unroll
    for (int o = 1; o < 256; o <<= 1) {
        int v = (t >= o) ? sh[t - o] : 0;
        __syncthreads();
        sh[t] += v;
        __syncthreads();
    }
    if (t < NBLK) g_boff[t] = sh[t] - c;
}

// ---------------- scan stage 3 ---------------------------------------------
__global__ __launch_bounds__(256) void k_scan3() {
    int i = blockIdx.x * 256 + threadIdx.x;
    if (i < NN) {
        int o = g_pre[i] + g_boff[blockIdx.x];
        g_off[i] = o;
        g_pos[i] = o;
    }
}

// ---------------- kernel 2: ht = h @ W, fused alpha_i/alpha_j epilogue -----
__global__ void k_gemm(const float* __restrict__ h, const float* __restrict__ W,
                       const float* __restrict__ a) {
    __shared__ float As[8][128];
    __shared__ float Bs[8][128];
    __shared__ float s_ai[512];
    __shared__ float s_aj[512];
    int row0 = blockIdx.x * 128;
    int t = threadIdx.x;
    int tr = t >> 4;
    int tc = t & 15;
    s_ai[t] = 0.0f; s_ai[t + 256] = 0.0f;
    s_aj[t] = 0.0f; s_aj[t + 256] = 0.0f;

    float acc[8][8];
    #pragma unroll
    for (int i = 0; i < 8; i++)
        #pragma unroll
        for (int j = 0; j < 8; j++) acc[i][j] = 0.0f;

    for (int k0 = 0; k0 < KF; k0 += 8) {
        {
            int r = t >> 1;
            int kk = (t & 1) * 4;
            float4 hv = make_float4(0.f, 0.f, 0.f, 0.f);
            if (row0 + r < NN)
                hv = *(const float4*)(h + (size_t)(row0 + r) * KF + k0 + kk);
            As[kk + 0][r] = hv.x; As[kk + 1][r] = hv.y;
            As[kk + 2][r] = hv.z; As[kk + 3][r] = hv.w;
            int o = t * 4;
            *(float4*)(&Bs[0][0] + o) = *(const float4*)(W + (size_t)k0 * HF + o);
        }
        __syncthreads();
        #pragma unroll
        for (int k = 0; k < 8; k++) {
            float av[8], bv[8];
            *(float4*)(av)     = *(const float4*)&As[k][tr * 8];
            *(float4*)(av + 4) = *(const float4*)&As[k][tr * 8 + 4];
            *(float4*)(bv)     = *(const float4*)&Bs[k][tc * 8];
            *(float4*)(bv + 4) = *(const float4*)&Bs[k][tc * 8 + 4];
            #pragma unroll
            for (int i = 0; i < 8; i++)
                #pragma unroll
                for (int j = 0; j < 8; j++)
                    acc[i][j] += av[i] * bv[j];
        }
        __syncthreads();
    }

    int h0 = tc >> 2;
    float wi[8], wj[8];
    #pragma unroll
    for (int j = 0; j < 8; j++) {
        int cm = (tc * 8 + j) & 31;
        wi[j] = __ldg(&a[h0 * 96 + cm]);
        wj[j] = __ldg(&a[h0 * 96 + 32 + cm]);
    }

    #pragma unroll
    for (int i = 0; i < 8; i++) {
        int r = row0 + tr * 8 + i;
        float pi = 0.0f, pj = 0.0f;
        #pragma unroll
        for (int j = 0; j < 8; j++) {
            pi += acc[i][j] * wi[j];
            pj += acc[i][j] * wj[j];
        }
        int ridx = (tr * 8 + i) * 4 + h0;
        atomicAdd(&s_ai[ridx], pi);
        atomicAdd(&s_aj[ridx], pj);
        if (r < NN) {
            float4* dst = (float4*)(g_ht + (size_t)r * HF + tc * 8);
            dst[0] = make_float4(acc[i][0], acc[i][1], acc[i][2], acc[i][3]);
            dst[1] = make_float4(acc[i][4], acc[i][5], acc[i][6], acc[i][7]);
        }
    }
    __syncthreads();
    #pragma unroll
    for (int s = 0; s < 2; s++) {
        int u = t + s * 256;
        int r = row0 + (u >> 2);
        if (r < NN) {
            g_ai[r * 4 + (u & 3)] = s_ai[u];
            g_aj[r * 4 + (u & 3)] = s_aj[u];
        }
    }
}

// ---------------- kernel 3: edge scores + global max + ticketed place ------
__global__ __launch_bounds__(256) void k_edge(const int* __restrict__ ei,
                                              const float* __restrict__ ea) {
    __shared__ float svc[NH * EF + NH];
    if (threadIdx.x < NH * EF + NH) svc[threadIdx.x] = g_vc[threadIdx.x];
    __syncthreads();

    int e = blockIdx.x * blockDim.x + threadIdx.x;
    float m = -1e30f;
    if (e < NE) {
        int row = ei[e];
        int col = ei[NE + e];
        float s0 = svc[128], s1 = svc[129], s2 = svc[130], s3 = svc[131];
        #pragma unroll
        for (int q = 0; q < 8; q++) {
            float4 x = *(const float4*)(ea + (size_t)e * EF + q * 4);
            int k = q * 4;
            s0 += x.x * svc[0*EF+k] + x.y * svc[0*EF+k+1] + x.z * svc[0*EF+k+2] + x.w * svc[0*EF+k+3];
            s1 += x.x * svc[1*EF+k] + x.y * svc[1*EF+k+1] + x.z * svc[1*EF+k+2] + x.w * svc[1*EF+k+3];
            s2 += x.x * svc[2*EF+k] + x.y * svc[2*EF+k+1] + x.z * svc[2*EF+k+2] + x.w * svc[2*EF+k+3];
            s3 += x.x * svc[3*EF+k] + x.y * svc[3*EF+k+1] + x.z * svc[3*EF+k+2] + x.w * svc[3*EF+k+3];
        }
        float4 ai = *(const float4*)(g_ai + (size_t)row * NH);
        float4 aj = *(const float4*)(g_aj + (size_t)col * NH);
        s0 += ai.x + aj.x; s1 += ai.y + aj.y; s2 += ai.z + aj.z; s3 += ai.w + aj.w;
        s0 = (s0 > 0.f) ? s0 : 0.2f * s0;
        s1 = (s1 > 0.f) ? s1 : 0.2f * s1;
        s2 = (s2 > 0.f) ? s2 : 0.2f * s2;
        s3 = (s3 > 0.f) ? s3 : 0.2f * s3;
        int p = atomicAdd(&g_pos[row], 1);
        *(float4*)(g_s + (size_t)p * NH) = make_float4(s0, s1, s2, s3);
        g_col[p] = col;
        g_eid[p] = e;
        m = fmaxf(fmaxf(s0, s1), fmaxf(s2, s3));
    }
    #pragma unroll
    for (int o = 16; o; o >>= 1) m = fmaxf(m, __shfl_xor_sync(0xffffffffu, m, o));
    __shared__ float smax[8];
    if ((threadIdx.x & 31) == 0) smax[threadIdx.x >> 5] = m;
    __syncthreads();
    if (threadIdx.x == 0) {
        float bm = smax[0];
        #pragma unroll
        for (int w = 1; w < 8; w++) bm = fmaxf(bm, smax[w]);
        atomicMax(&g_maxbits, f2o(bm));
    }
}

// ---------------- kernel 4: warp-per-node gather (denom, att, h_out, elu) --
__global__ __launch_bounds__(128) void k_nodes(float* __restrict__ out_h,
                                               float* __restrict__ out_att) {
    int n = blockIdx.x * 4 + (threadIdx.x >> 5);   // grid = NN/4 exactly
    int lane = threadIdx.x & 31;
    int start = g_off[n];
    int cnt = g_cnt[n];
    float M = o2f(g_maxbits);

    // denom per head: flattened s[start*4 .. +cnt*4); element i has head i&3
    float s = 0.0f;
    const float* sbase = g_s + (size_t)start * 4;
    for (int i = lane; i < cnt * 4; i += 32) s += __expf(sbase[i] - M);
    s += __shfl_xor_sync(0xffffffffu, s, 4);
    s += __shfl_xor_sync(0xffffffffu, s, 8);
    s += __shfl_xor_sync(0xffffffffu, s, 16);
    float inv_h = 1.0f / (s + 1e-8f);                          // head = lane&3
    float my_inv = __shfl_sync(0xffffffffu, inv_h, lane >> 3); // head of my cols

    int myhead = lane >> 3;
    float4 acc = make_float4(0.f, 0.f, 0.f, 0.f);
    #pragma unroll 4
    for (int k = 0; k < cnt; k++) {
        size_t idx = (size_t)(start + k);
        int col = g_col[idx];                        // uniform broadcast load
        float w = __expf(g_s[idx * 4 + myhead] - M) * my_inv;
        if (lane < 4)
            out_att[(size_t)g_eid[idx] * 4 + lane] =
                __expf(g_s[idx * 4 + lane] - M) * inv_h;
        float4 x = *(const float4*)(g_ht + (size_t)col * HF + lane * 4);
        acc.x += w * x.x; acc.y += w * x.y;
        acc.z += w * x.z; acc.w += w * x.w;
    }
    acc.x = (acc.x > 0.f) ? acc.x : expm1f(acc.x);
    acc.y = (acc.y > 0.f) ? acc.y : expm1f(acc.y);
    acc.z = (acc.z > 0.f) ? acc.z : expm1f(acc.z);
    acc.w = (acc.w > 0.f) ? acc.w : expm1f(acc.w);
    *(float4*)(out_h + (size_t)n * HF + lane * 4) = acc;
}

// ---------------- launcher --------------------------------------------------
extern "C" void kernel_launch(void* const* d_in, const int* in_sizes, int n_in,
                              void* d_out, int out_size) {
    (void)in_sizes; (void)n_in; (void)out_size;
    const float* h  = (const float*)d_in[0];
    const int*   ei = (const int*)d_in[1];
    const float* ea = (const float*)d_in[2];
    const float* W  = (const float*)d_in[3];
    const float* a  = (const float*)d_in[4];
    const float* eW = (const float*)d_in[5];
    const float* eb = (const float*)d_in[6];

    float* out_h   = (float*)d_out;                       // [NN, 128]
    float* out_att = (float*)d_out + (size_t)NN * HF;     // [NE, 4]

    k_init<<<200, 256>>>(eW, a, eb);
    k_count<<<(NE + 255) / 256, 256>>>(ei);
    k_scan1<<<NBLK, 256>>>();
    k_scan2<<<1, 256>>>();
    k_scan3<<<NBLK, 256>>>();
    k_gemm<<<(NN + 127) / 128, 256>>>(h, W, a);
    k_edge<<<(NE + 255) / 256, 256>>>(ei, ea);
    k_nodes<<<NN / 4, 128>>>(out_h, out_att);
}

// round 6
// speedup vs baseline: 1.1377x; 1.1377x over previous
#include <cuda_runtime.h>
#include <math.h>

#define NN 50000
#define NE 800000
#define KF 128          // IN_F
#define HF 128          // HEADS * OUT_F
#define NH 4
#define OF 32
#define EF 32
#define NBLK 196        // ceil(NN/256)

// ---------------- scratch (device globals: allocation-free) ----------------
__device__ float g_ht[(size_t)NN * HF];                 // 25.6 MB
__device__ __align__(16) float g_ai[NN * NH];
__device__ __align__(16) float g_aj[NN * NH];
__device__ __align__(16) float g_s[(size_t)NE * NH];    // raw scores, ROW-SORTED
__device__ int   g_col[NE];                             // sorted -> col
__device__ int   g_eid[NE];                             // sorted -> edge id
__device__ int   g_cnt[NN];
__device__ int   g_pre[NN];
__device__ int   g_off[NN];
__device__ int   g_pos[NN];
__device__ int   g_bsum[NBLK];
__device__ __align__(16) float g_vct[EF * NH];          // transposed: [k][head]
__device__ __align__(16) float g_c4[NH];                // bias term per head
__device__ unsigned int g_maxbits;

__device__ __forceinline__ unsigned f2o(float x) {
    unsigned u = __float_as_uint(x);
    return (u & 0x80000000u) ? ~u : (u | 0x80000000u);
}
__device__ __forceinline__ float o2f(unsigned u) {
    return __uint_as_float((u & 0x80000000u) ? (u & 0x7fffffffu) : ~u);
}

// ---------------- kernel 0: init (vct transposed, c, reset max) ------------
__global__ void k_init(const float* __restrict__ eW, const float* __restrict__ a,
                       const float* __restrict__ eb) {
    int t = threadIdx.x;
    if (t < EF * NH) {                     // vct[k*4+h] = sum_f eW[k, h*32+f]*a_e[h][f]
        int k = t >> 2, h = t & 3;
        float s = 0.0f;
        #pragma unroll
        for (int f = 0; f < OF; f++)
            s += eW[k * HF + h * OF + f] * a[h * 96 + 64 + f];
        g_vct[t] = s;
    } else if (t < EF * NH + NH) {
        int h = t - EF * NH;
        float s = 0.0f;
        #pragma unroll
        for (int f = 0; f < OF; f++)
            s += eb[h * OF + f] * a[h * 96 + 64 + f];
        g_c4[h] = s;
    } else if (t == EF * NH + NH) {
        g_maxbits = 0u;
    }
}

// ---------------- kernel 1: row histogram ----------------------------------
__global__ __launch_bounds__(256) void k_count(const int* __restrict__ ei) {
    int e = blockIdx.x * blockDim.x + threadIdx.x;
    if (e < NE) atomicAdd(&g_cnt[ei[e]], 1);
}

// ---------------- scan stage 1: per-block prefix + block sums --------------
__global__ __launch_bounds__(256) void k_scan1() {
    __shared__ int sh[256];
    int t = threadIdx.x;
    int i = blockIdx.x * 256 + t;
    int c = (i < NN) ? g_cnt[i] : 0;
    sh[t] = c;
    __syncthreads();
    #pragma unroll
    for (int o = 1; o < 256; o <<= 1) {
        int v = (t >= o) ? sh[t - o] : 0;
        __syncthreads();
        sh[t] += v;
        __syncthreads();
    }
    if (i < NN) g_pre[i] = sh[t] - c;
    if (t == 255) g_bsum[blockIdx.x] = sh[255];
}

// ---------------- scan stage 2+3 merged: block base + final offsets --------
__global__ __launch_bounds__(256) void k_scan23() {
    __shared__ int sh[256];
    int t = threadIdx.x;
    sh[t] = (t < blockIdx.x) ? g_bsum[t] : 0;   // NBLK <= 256
    __syncthreads();
    #pragma unroll
    for (int o = 128; o; o >>= 1) {
        if (t < o) sh[t] += sh[t + o];
        __syncthreads();
    }
    int base = sh[0];
    int i = blockIdx.x * 256 + t;
    if (i < NN) {
        int o = g_pre[i] + base;
        g_off[i] = o;
        g_pos[i] = o;
    }
}

// ---------------- kernel 2: ht = h @ W, fused alpha_i/alpha_j epilogue -----
__global__ void k_gemm(const float* __restrict__ h, const float* __restrict__ W,
                       const float* __restrict__ a) {
    __shared__ float As[8][128];
    __shared__ float Bs[8][128];
    __shared__ float s_ai[512];
    __shared__ float s_aj[512];
    int row0 = blockIdx.x * 128;
    int t = threadIdx.x;
    int tr = t >> 4;
    int tc = t & 15;
    s_ai[t] = 0.0f; s_ai[t + 256] = 0.0f;
    s_aj[t] = 0.0f; s_aj[t + 256] = 0.0f;

    float acc[8][8];
    #pragma unroll
    for (int i = 0; i < 8; i++)
        #pragma unroll
        for (int j = 0; j < 8; j++) acc[i][j] = 0.0f;

    for (int k0 = 0; k0 < KF; k0 += 8) {
        {
            int r = t >> 1;
            int kk = (t & 1) * 4;
            float4 hv = make_float4(0.f, 0.f, 0.f, 0.f);
            if (row0 + r < NN)
                hv = *(const float4*)(h + (size_t)(row0 + r) * KF + k0 + kk);
            As[kk + 0][r] = hv.x; As[kk + 1][r] = hv.y;
            As[kk + 2][r] = hv.z; As[kk + 3][r] = hv.w;
            int o = t * 4;
            *(float4*)(&Bs[0][0] + o) = *(const float4*)(W + (size_t)k0 * HF + o);
        }
        __syncthreads();
        #pragma unroll
        for (int k = 0; k < 8; k++) {
            float av[8], bv[8];
            *(float4*)(av)     = *(const float4*)&As[k][tr * 8];
            *(float4*)(av + 4) = *(const float4*)&As[k][tr * 8 + 4];
            *(float4*)(bv)     = *(const float4*)&Bs[k][tc * 8];
            *(float4*)(bv + 4) = *(const float4*)&Bs[k][tc * 8 + 4];
            #pragma unroll
            for (int i = 0; i < 8; i++)
                #pragma unroll
                for (int j = 0; j < 8; j++)
                    acc[i][j] += av[i] * bv[j];
        }
        __syncthreads();
    }

    int h0 = tc >> 2;
    float wi[8], wj[8];
    #pragma unroll
    for (int j = 0; j < 8; j++) {
        int cm = (tc * 8 + j) & 31;
        wi[j] = __ldg(&a[h0 * 96 + cm]);
        wj[j] = __ldg(&a[h0 * 96 + 32 + cm]);
    }

    #pragma unroll
    for (int i = 0; i < 8; i++) {
        int r = row0 + tr * 8 + i;
        float pi = 0.0f, pj = 0.0f;
        #pragma unroll
        for (int j = 0; j < 8; j++) {
            pi += acc[i][j] * wi[j];
            pj += acc[i][j] * wj[j];
        }
        int ridx = (tr * 8 + i) * 4 + h0;
        atomicAdd(&s_ai[ridx], pi);
        atomicAdd(&s_aj[ridx], pj);
        if (r < NN) {
            float4* dst = (float4*)(g_ht + (size_t)r * HF + tc * 8);
            dst[0] = make_float4(acc[i][0], acc[i][1], acc[i][2], acc[i][3]);
            dst[1] = make_float4(acc[i][4], acc[i][5], acc[i][6], acc[i][7]);
        }
    }
    __syncthreads();
    #pragma unroll
    for (int s = 0; s < 2; s++) {
        int u = t + s * 256;
        int r = row0 + (u >> 2);
        if (r < NN) {
            g_ai[r * 4 + (u & 3)] = s_ai[u];
            g_aj[r * 4 + (u & 3)] = s_aj[u];
        }
    }
}

// ---------------- kernel 3: edge scores + global max + ticketed place ------
__global__ __launch_bounds__(256) void k_edge(const int* __restrict__ ei,
                                              const float* __restrict__ ea) {
    __shared__ float4 svct[EF];
    __shared__ float4 sc4;
    if (threadIdx.x < EF) svct[threadIdx.x] = *(const float4*)(g_vct + threadIdx.x * 4);
    if (threadIdx.x == EF) sc4 = *(const float4*)g_c4;
    __syncthreads();

    int e = blockIdx.x * blockDim.x + threadIdx.x;
    float m = -1e30f;
    if (e < NE) {
        int row = ei[e];
        int col = ei[NE + e];
        float4 s4 = sc4;
        #pragma unroll
        for (int q = 0; q < 8; q++) {
            float4 x = *(const float4*)(ea + (size_t)e * EF + q * 4);
            float4 v0 = svct[q * 4 + 0];
            float4 v1 = svct[q * 4 + 1];
            float4 v2 = svct[q * 4 + 2];
            float4 v3 = svct[q * 4 + 3];
            s4.x += x.x * v0.x + x.y * v1.x + x.z * v2.x + x.w * v3.x;
            s4.y += x.x * v0.y + x.y * v1.y + x.z * v2.y + x.w * v3.y;
            s4.z += x.x * v0.z + x.y * v1.z + x.z * v2.z + x.w * v3.z;
            s4.w += x.x * v0.w + x.y * v1.w + x.z * v2.w + x.w * v3.w;
        }
        float4 ai = *(const float4*)(g_ai + (size_t)row * NH);
        float4 aj = *(const float4*)(g_aj + (size_t)col * NH);
        s4.x += ai.x + aj.x; s4.y += ai.y + aj.y;
        s4.z += ai.z + aj.z; s4.w += ai.w + aj.w;
        s4.x = (s4.x > 0.f) ? s4.x : 0.2f * s4.x;
        s4.y = (s4.y > 0.f) ? s4.y : 0.2f * s4.y;
        s4.z = (s4.z > 0.f) ? s4.z : 0.2f * s4.z;
        s4.w = (s4.w > 0.f) ? s4.w : 0.2f * s4.w;
        int p = atomicAdd(&g_pos[row], 1);
        *(float4*)(g_s + (size_t)p * NH) = s4;
        g_col[p] = col;
        g_eid[p] = e;
        m = fmaxf(fmaxf(s4.x, s4.y), fmaxf(s4.z, s4.w));
    }
    #pragma unroll
    for (int o = 16; o; o >>= 1) m = fmaxf(m, __shfl_xor_sync(0xffffffffu, m, o));
    __shared__ float smax[8];
    if ((threadIdx.x & 31) == 0) smax[threadIdx.x >> 5] = m;
    __syncthreads();
    if (threadIdx.x == 0) {
        float bm = smax[0];
        #pragma unroll
        for (int w = 1; w < 8; w++) bm = fmaxf(bm, smax[w]);
        atomicMax(&g_maxbits, f2o(bm));
    }
}

// ---------------- kernel 4: warp-per-node gather (denom, att, h_out, elu) --
__global__ __launch_bounds__(128) void k_nodes(float* __restrict__ out_h,
                                               float* __restrict__ out_att) {
    __shared__ float s_att[4][32][4];
    __shared__ int   s_col[4][32];
    int w = threadIdx.x >> 5;
    int n = blockIdx.x * 4 + w;            // grid = NN/4 exactly
    int lane = threadIdx.x & 31;
    int start = g_off[n];
    int cnt = g_cnt[n];
    float M = o2f(g_maxbits);

    // denom per head: flattened s[start*4 .. +cnt*4); element i has head i&3
    float s = 0.0f;
    const float* sbase = g_s + (size_t)start * 4;
    for (int i = lane; i < cnt * 4; i += 32) s += __expf(sbase[i] - M);
    s += __shfl_xor_sync(0xffffffffu, s, 4);
    s += __shfl_xor_sync(0xffffffffu, s, 8);
    s += __shfl_xor_sync(0xffffffffu, s, 16);
    float inv_h = 1.0f / (s + 1e-8f);                      // head = lane&3
    float i0 = __shfl_sync(0xffffffffu, inv_h, 0);
    float i1 = __shfl_sync(0xffffffffu, inv_h, 1);
    float i2 = __shfl_sync(0xffffffffu, inv_h, 2);
    float i3 = __shfl_sync(0xffffffffu, inv_h, 3);

    int myhead = lane >> 3;
    float4 acc = make_float4(0.f, 0.f, 0.f, 0.f);
    for (int k0 = 0; k0 < cnt; k0 += 32) {
        int k = k0 + lane;
        if (k < cnt) {
            size_t idx = (size_t)(start + k);
            float4 sr = *(const float4*)(g_s + idx * 4);
            float4 at = make_float4(__expf(sr.x - M) * i0, __expf(sr.y - M) * i1,
                                    __expf(sr.z - M) * i2, __expf(sr.w - M) * i3);
            *(float4*)(out_att + (size_t)g_eid[idx] * 4) = at;
            *(float4*)(&s_att[w][lane][0]) = at;
            s_col[w][lane] = g_col[idx];
        }
        __syncwarp();
        int lim = min(32, cnt - k0);
        #pragma unroll 4
        for (int j = 0; j < lim; j++) {
            int col  = s_col[w][j];
            float wt = s_att[w][j][myhead];
            float4 x = *(const float4*)(g_ht + (size_t)col * HF + lane * 4);
            acc.x += wt * x.x; acc.y += wt * x.y;
            acc.z += wt * x.z; acc.w += wt * x.w;
        }
        __syncwarp();
    }
    acc.x = (acc.x > 0.f) ? acc.x : expm1f(acc.x);
    acc.y = (acc.y > 0.f) ? acc.y : expm1f(acc.y);
    acc.z = (acc.z > 0.f) ? acc.z : expm1f(acc.z);
    acc.w = (acc.w > 0.f) ? acc.w : expm1f(acc.w);
    *(float4*)(out_h + (size_t)n * HF + lane * 4) = acc;
}

// ---------------- launcher --------------------------------------------------
extern "C" void kernel_launch(void* const* d_in, const int* in_sizes, int n_in,
                              void* d_out, int out_size) {
    (void)in_sizes; (void)n_in; (void)out_size;
    const float* h  = (const float*)d_in[0];
    const int*   ei = (const int*)d_in[1];
    const float* ea = (const float*)d_in[2];
    const float* W  = (const float*)d_in[3];
    const float* a  = (const float*)d_in[4];
    const float* eW = (const float*)d_in[5];
    const float* eb = (const float*)d_in[6];

    float* out_h   = (float*)d_out;                       // [NN, 128]
    float* out_att = (float*)d_out + (size_t)NN * HF;     // [NE, 4]

    void* cnt_ptr = 0;
    cudaGetSymbolAddress(&cnt_ptr, g_cnt);
    cudaMemsetAsync(cnt_ptr, 0, NN * sizeof(int), 0);

    k_init<<<1, 160>>>(eW, a, eb);
    k_count<<<(NE + 255) / 256, 256>>>(ei);
    k_scan1<<<NBLK, 256>>>();
    k_scan23<<<NBLK, 256>>>();
    k_gemm<<<(NN + 127) / 128, 256>>>(h, W, a);
    k_edge<<<(NE + 255) / 256, 256>>>(ei, ea);
    k_nodes<<<NN / 4, 128>>>(out_h, out_att);
}